// round 8
// baseline (speedup 1.0000x reference)
#include <cuda_runtime.h>
#include <cuda_fp16.h>
#include <cstdint>
#include <math.h>

// Problem dims (fixed)
#define BB 4
#define SS 4096
#define DD 1024
#define AA 1024
#define MTOT (BB*SS)   // 16384

// ---------------------------------------------------------------------------
// Device scratch
// ---------------------------------------------------------------------------
__device__ float g_Vf[(size_t)MTOT * AA];                 // 64 MB
__device__ float g_S [(size_t)BB * SS * SS];              // 256 MB scores
__device__ __half g_Xhi[(size_t)MTOT * DD];
__device__ __half g_Xlo[(size_t)MTOT * DD];
__device__ __half g_Wh[3][(size_t)AA * DD];               // (16*W)^T splits [A,D]
__device__ __half g_Wl[3][(size_t)AA * DD];
__device__ __half g_Qhi[(size_t)MTOT * AA];
__device__ __half g_Qlo[(size_t)MTOT * AA];
__device__ __half g_Khi[(size_t)MTOT * AA];
__device__ __half g_Klo[(size_t)MTOT * AA];
__device__ __half g_Vthi[(size_t)BB * AA * SS];           // V^T per batch [A,S]
__device__ __half g_Phi[(size_t)BB * SS * SS];            // 128 MB

// ---------------------------------------------------------------------------
// Helpers
// ---------------------------------------------------------------------------
__device__ __forceinline__ uint32_t smem_u32(const void* p) {
    uint32_t a;
    asm("{ .reg .u64 t; cvta.to.shared.u64 t, %1; cvt.u32.u64 %0, t; }" : "=r"(a) : "l"(p));
    return a;
}

#define CP_ASYNC16(saddr, gaddr) \
    asm volatile("cp.async.cg.shared.global [%0], [%1], 16;" :: "r"(saddr), "l"(gaddr))
#define CP_COMMIT()  asm volatile("cp.async.commit_group;" ::: "memory")
#define CP_WAIT1()   asm volatile("cp.async.wait_group 1;" ::: "memory")
#define CP_WAIT0()   asm volatile("cp.async.wait_group 0;" ::: "memory")

// f32-accumulate HMMA (main term)
#define MMA_F16(c, a, b) \
    asm volatile("mma.sync.aligned.m16n8k16.row.col.f32.f16.f16.f32 " \
        "{%0,%1,%2,%3}, {%4,%5,%6,%7}, {%8,%9}, {%0,%1,%2,%3};" \
        : "+f"((c)[0]), "+f"((c)[1]), "+f"((c)[2]), "+f"((c)[3]) \
        : "r"((a)[0]), "r"((a)[1]), "r"((a)[2]), "r"((a)[3]), \
          "r"((b)[0]), "r"((b)[1]))

// f16-accumulate HMMA (correction terms; magnitudes ~2^-11 of main — safe)
#define MMA_F16ACC(c, a, b) \
    asm volatile("mma.sync.aligned.m16n8k16.row.col.f16.f16.f16.f16 " \
        "{%0,%1}, {%2,%3,%4,%5}, {%6,%7}, {%0,%1};" \
        : "+r"((c)[0]), "+r"((c)[1]) \
        : "r"((a)[0]), "r"((a)[1]), "r"((a)[2]), "r"((a)[3]), \
          "r"((b)[0]), "r"((b)[1]))

// ---------------------------------------------------------------------------
// HMMA GEMM, fp16 hi/lo split, term count NT:
//   NT=3: AhBh (f32 acc) + AlBh + AhBl (f16 acc corrections)
//   NT=1: AhBh only
// C[M,N] = A[M,K] * B[N,K]^T, K-major. CTA tile 128x128, KC=32,
// 2-stage cp.async double buffer, 1 CTA/SM (reg headroom for f16 corr accs).
// 8 warps as 4(m) x 2(n); warp tile 32x64 = 2 m16 x 8 n8 mma tiles.
// ---------------------------------------------------------------------------
#define KC    32
#define ROWB  80                              // 32 fp16 (64B) + 16B pad
#define TILE_T (128 * ROWB)                   // 10240 B

__device__ __forceinline__ void load_tile32(const __half* __restrict__ g,
                                            int ldK, char* sb, int tid)
{
#pragma unroll
    for (int i = 0; i < 2; i++) {
        int ch = tid + i * 256;               // 0..511
        int row = ch >> 2, c = ch & 3;
        CP_ASYNC16(smem_u32(sb + row * ROWB + c * 16),
                   g + (size_t)row * ldK + c * 8);
    }
}

template <int NT>
__device__ __forceinline__ void load_stage(const __half* pAh, const __half* pAl,
                                           const __half* pBh, const __half* pBl,
                                           int k0, int K, char* sp, int tid)
{
    load_tile32(pAh + k0, K, sp, tid);
    if (NT == 3) {
        load_tile32(pAl + k0, K, sp + TILE_T,     tid);
        load_tile32(pBh + k0, K, sp + 2 * TILE_T, tid);
        load_tile32(pBl + k0, K, sp + 3 * TILE_T, tid);
    } else {
        load_tile32(pBh + k0, K, sp + TILE_T, tid);
    }
    CP_COMMIT();
}

template <int NT, bool SPLIT_OUT>
__global__ __launch_bounds__(256, 1)
void gemm_mma(const __half* __restrict__ Ahi, const __half* __restrict__ Alo,
              const __half* __restrict__ Bhi, const __half* __restrict__ Blo,
              float* __restrict__ C,
              __half* __restrict__ Chi, __half* __restrict__ Clo,
              int K, int ldC,
              long long sA, long long sB, long long sC, float oscale)
{
    constexpr int STG = (NT == 3 ? 4 : 2) * TILE_T;
    extern __shared__ __align__(128) char smem[];
    const int tid = threadIdx.x;
    const int wid = tid >> 5, lane = tid & 31;
    const int wm = wid & 3, wn = wid >> 2;    // 4(m) x 2(n)
    const int m0 = blockIdx.y * 128;
    const int n0 = blockIdx.x * 128;

    const __half* pAh = Ahi + (size_t)blockIdx.z * sA + (size_t)m0 * K;
    const __half* pAl = (NT == 3) ? Alo + (size_t)blockIdx.z * sA + (size_t)m0 * K : nullptr;
    const __half* pBh = Bhi + (size_t)blockIdx.z * sB + (size_t)n0 * K;
    const __half* pBl = (NT == 3) ? Blo + (size_t)blockIdx.z * sB + (size_t)n0 * K : nullptr;

    float acc[2][8][4];
    uint32_t corr[2][8][2];                    // f16x2 correction accumulators
#pragma unroll
    for (int mt = 0; mt < 2; mt++)
#pragma unroll
        for (int nt = 0; nt < 8; nt++) {
#pragma unroll
            for (int j = 0; j < 4; j++) acc[mt][nt][j] = 0.0f;
            corr[mt][nt][0] = 0u; corr[mt][nt][1] = 0u;
        }

    const int nch = K >> 5;

    load_stage<NT>(pAh, pAl, pBh, pBl, 0,  K, smem,       tid);
    load_stage<NT>(pAh, pAl, pBh, pBl, KC, K, smem + STG, tid);

    const int r  = lane >> 2;        // 0..7
    const int kq = lane & 3;         // 0..3

    for (int c = 0; c < nch; ++c) {
        if (c + 1 < nch) CP_WAIT1(); else CP_WAIT0();
        __syncthreads();

        const char* sp  = smem + (c & 1) * STG;
        const char* sAh = sp;
        const char* sAl = sp + TILE_T;                       // NT==3
        const char* sBh = sp + (NT == 3 ? 2 : 1) * TILE_T;
        const char* sBl = sp + 3 * TILE_T;                   // NT==3

#pragma unroll
        for (int ks = 0; ks < 2; ++ks) {
            const int kb = ks * 32 + kq * 4;

            uint32_t ah[2][4], al[2][4];
#pragma unroll
            for (int mt = 0; mt < 2; mt++) {
                const int row = wm * 32 + mt * 16 + r;
                const char* a0 = sAh + row * ROWB + kb;
                const char* a1 = sAh + (row + 8) * ROWB + kb;
                ah[mt][0] = *(const uint32_t*)(a0);
                ah[mt][1] = *(const uint32_t*)(a1);
                ah[mt][2] = *(const uint32_t*)(a0 + 16);
                ah[mt][3] = *(const uint32_t*)(a1 + 16);
                if (NT == 3) {
                    const char* b0 = sAl + row * ROWB + kb;
                    const char* b1 = sAl + (row + 8) * ROWB + kb;
                    al[mt][0] = *(const uint32_t*)(b0);
                    al[mt][1] = *(const uint32_t*)(b1);
                    al[mt][2] = *(const uint32_t*)(b0 + 16);
                    al[mt][3] = *(const uint32_t*)(b1 + 16);
                }
            }
#pragma unroll
            for (int nt = 0; nt < 8; nt++) {
                const int n = wn * 64 + nt * 8 + r;
                uint32_t bh[2];
                const char* p = sBh + n * ROWB + kb;
                bh[0] = *(const uint32_t*)(p);
                bh[1] = *(const uint32_t*)(p + 16);
#pragma unroll
                for (int mt = 0; mt < 2; mt++)
                    MMA_F16(acc[mt][nt], ah[mt], bh);
                if (NT == 3) {
                    uint32_t bl[2];
                    const char* q = sBl + n * ROWB + kb;
                    bl[0] = *(const uint32_t*)(q);
                    bl[1] = *(const uint32_t*)(q + 16);
#pragma unroll
                    for (int mt = 0; mt < 2; mt++) {
                        MMA_F16ACC(corr[mt][nt], al[mt], bh);
                        MMA_F16ACC(corr[mt][nt], ah[mt], bl);
                    }
                }
            }
        }

        if (c + 2 < nch) {
            __syncthreads();
            load_stage<NT>(pAh, pAl, pBh, pBl, (c + 2) * KC, K,
                           smem + (c & 1) * STG, tid);
        }
    }

    // fold f16 corrections into f32 accumulators
    if (NT == 3) {
#pragma unroll
        for (int mt = 0; mt < 2; mt++)
#pragma unroll
            for (int nt = 0; nt < 8; nt++) {
                float2 c0 = __half22float2(*reinterpret_cast<__half2*>(&corr[mt][nt][0]));
                float2 c1 = __half22float2(*reinterpret_cast<__half2*>(&corr[mt][nt][1]));
                acc[mt][nt][0] += c0.x; acc[mt][nt][1] += c0.y;
                acc[mt][nt][2] += c1.x; acc[mt][nt][3] += c1.y;
            }
    }

    // epilogue
    const int cq = (lane & 3) * 2;
    if (!SPLIT_OUT) {
        float* Cw = C + (size_t)blockIdx.z * sC
                      + (size_t)(m0 + wm * 32) * ldC + n0 + wn * 64;
#pragma unroll
        for (int mt = 0; mt < 2; mt++)
#pragma unroll
            for (int nt = 0; nt < 8; nt++) {
                float* p0 = Cw + (size_t)(mt * 16 + r) * ldC + nt * 8 + cq;
                float* p1 = p0 + 8 * (size_t)ldC;
                *(float2*)p0 = make_float2(acc[mt][nt][0] * oscale, acc[mt][nt][1] * oscale);
                *(float2*)p1 = make_float2(acc[mt][nt][2] * oscale, acc[mt][nt][3] * oscale);
            }
    } else {
        const size_t off = (size_t)blockIdx.z * sC
                         + (size_t)(m0 + wm * 32) * ldC + n0 + wn * 64;
        __half* Hw = Chi + off;
        __half* Lw = Clo + off;
#pragma unroll
        for (int mt = 0; mt < 2; mt++)
#pragma unroll
            for (int nt = 0; nt < 8; nt++) {
                const size_t o0 = (size_t)(mt * 16 + r) * ldC + nt * 8 + cq;
                const size_t o1 = o0 + 8 * (size_t)ldC;
                float x0 = acc[mt][nt][0] * oscale, x1 = acc[mt][nt][1] * oscale;
                float x2 = acc[mt][nt][2] * oscale, x3 = acc[mt][nt][3] * oscale;
                __half h0 = __float2half_rn(x0), h1 = __float2half_rn(x1);
                __half h2 = __float2half_rn(x2), h3 = __float2half_rn(x3);
                *(__half2*)(Hw + o0) = __halves2half2(h0, h1);
                *(__half2*)(Hw + o1) = __halves2half2(h2, h3);
                __half l0 = __float2half_rn(x0 - __half2float(h0));
                __half l1 = __float2half_rn(x1 - __half2float(h1));
                __half l2 = __float2half_rn(x2 - __half2float(h2));
                __half l3 = __float2half_rn(x3 - __half2float(h3));
                *(__half2*)(Lw + o0) = __halves2half2(l0, l1);
                *(__half2*)(Lw + o1) = __halves2half2(l2, l3);
            }
    }
}

// ---------------------------------------------------------------------------
// fp32 -> fp16 hi/lo split (elementwise)
// ---------------------------------------------------------------------------
__global__ __launch_bounds__(256)
void split_plain(const float* __restrict__ in, __half* __restrict__ hi,
                 __half* __restrict__ lo, size_t n)
{
    size_t i = ((size_t)blockIdx.x * 256 + threadIdx.x) * 4;
    if (i >= n) return;
    float4 x = *(const float4*)(in + i);
    __half h0 = __float2half_rn(x.x), h1 = __float2half_rn(x.y);
    __half h2 = __float2half_rn(x.z), h3 = __float2half_rn(x.w);
    __half l0 = __float2half_rn(x.x - __half2float(h0));
    __half l1 = __float2half_rn(x.y - __half2float(h1));
    __half l2 = __float2half_rn(x.z - __half2float(h2));
    __half l3 = __float2half_rn(x.w - __half2float(h3));
    *(__half2*)(hi + i)     = __halves2half2(h0, h1);
    *(__half2*)(hi + i + 2) = __halves2half2(h2, h3);
    *(__half2*)(lo + i)     = __halves2half2(l0, l1);
    *(__half2*)(lo + i + 2) = __halves2half2(l2, l3);
}

// ---------------------------------------------------------------------------
// fp32 [R,C] -> transposed, scaled fp16 hi/lo [C,R]
// ---------------------------------------------------------------------------
__global__ __launch_bounds__(256)
void transpose_split(const float* __restrict__ in, __half* __restrict__ hiT,
                     __half* __restrict__ loT, int R, int C, float scale)
{
    __shared__ float t[32][33];
    const int r0 = blockIdx.y * 32, c0 = blockIdx.x * 32;
    const int tx = threadIdx.x & 31, ty = threadIdx.x >> 5;
#pragma unroll
    for (int i = ty; i < 32; i += 8)
        t[i][tx] = in[(size_t)(r0 + i) * C + c0 + tx];
    __syncthreads();
#pragma unroll
    for (int i = ty; i < 32; i += 8) {
        float x = t[tx][i] * scale;
        __half h = __float2half_rn(x);
        __half l = __float2half_rn(x - __half2float(h));
        size_t o = (size_t)(c0 + i) * R + r0 + tx;
        hiT[o] = h; loT[o] = l;
    }
}

// fp32 [R,C] -> transposed fp16 hi only [C,R] (batched via z)
__global__ __launch_bounds__(256)
void transpose_hi(const float* __restrict__ in, __half* __restrict__ hiT,
                  int R, int C, long long sIn, long long sOut)
{
    __shared__ float t[32][33];
    in  += (size_t)blockIdx.z * sIn;
    hiT += (size_t)blockIdx.z * sOut;
    const int r0 = blockIdx.y * 32, c0 = blockIdx.x * 32;
    const int tx = threadIdx.x & 31, ty = threadIdx.x >> 5;
#pragma unroll
    for (int i = ty; i < 32; i += 8)
        t[i][tx] = in[(size_t)(r0 + i) * C + c0 + tx];
    __syncthreads();
#pragma unroll
    for (int i = ty; i < 32; i += 8)
        hiT[(size_t)(c0 + i) * R + r0 + tx] = __float2half_rn(t[tx][i]);
}

// ---------------------------------------------------------------------------
// Row softmax (4096 cols), write fp16 (hi only)
// ---------------------------------------------------------------------------
__global__ __launch_bounds__(256)
void softmax_f16(const float* __restrict__ S, __half* __restrict__ Ph)
{
    const size_t row = blockIdx.x;
    const float* p = S + row * (size_t)SS;
    const int tid = threadIdx.x;

    float4 v[4];
    float m = -INFINITY;
#pragma unroll
    for (int i = 0; i < 4; i++) {
        v[i] = ((const float4*)p)[tid + i * 256];
        m = fmaxf(m, fmaxf(fmaxf(v[i].x, v[i].y), fmaxf(v[i].z, v[i].w)));
    }
    __shared__ float red[256];
    red[tid] = m; __syncthreads();
#pragma unroll
    for (int s = 128; s > 0; s >>= 1) {
        if (tid < s) red[tid] = fmaxf(red[tid], red[tid + s]);
        __syncthreads();
    }
    const float rowmax = red[0];
    __syncthreads();

    float sum = 0.0f;
#pragma unroll
    for (int i = 0; i < 4; i++) {
        v[i].x = __expf(v[i].x - rowmax);
        v[i].y = __expf(v[i].y - rowmax);
        v[i].z = __expf(v[i].z - rowmax);
        v[i].w = __expf(v[i].w - rowmax);
        sum += v[i].x + v[i].y + v[i].z + v[i].w;
    }
    red[tid] = sum; __syncthreads();
#pragma unroll
    for (int s = 128; s > 0; s >>= 1) {
        if (tid < s) red[tid] += red[tid + s];
        __syncthreads();
    }
    const float inv = 1.0f / red[0];
    __syncthreads();

#pragma unroll
    for (int i = 0; i < 4; i++) {
        size_t o = row * (size_t)SS + (size_t)(tid + i * 256) * 4;
        *(__half2*)(Ph + o)     = __halves2half2(__float2half_rn(v[i].x * inv),
                                                 __float2half_rn(v[i].y * inv));
        *(__half2*)(Ph + o + 2) = __halves2half2(__float2half_rn(v[i].z * inv),
                                                 __float2half_rn(v[i].w * inv));
    }
}

// ---------------------------------------------------------------------------
// kernel_launch — graph-capturable pipeline
// ---------------------------------------------------------------------------
extern "C" void kernel_launch(void* const* d_in, const int* in_sizes, int n_in,
                              void* d_out, int out_size)
{
    const float* X  = (const float*)d_in[0];
    const float* Wq = (const float*)d_in[1];
    const float* Wk = (const float*)d_in[2];
    const float* Wv = (const float*)d_in[3];
    float* out = (float*)d_out;

    float *Vf, *Sc;
    __half *Xhi, *Xlo, *Wh, *Wl, *Qhi, *Qlo, *Khi, *Klo, *Vthi, *Phi;
    cudaGetSymbolAddress((void**)&Vf, g_Vf);
    cudaGetSymbolAddress((void**)&Sc, g_S);
    cudaGetSymbolAddress((void**)&Xhi, g_Xhi);
    cudaGetSymbolAddress((void**)&Xlo, g_Xlo);
    cudaGetSymbolAddress((void**)&Wh, g_Wh);
    cudaGetSymbolAddress((void**)&Wl, g_Wl);
    cudaGetSymbolAddress((void**)&Qhi, g_Qhi);
    cudaGetSymbolAddress((void**)&Qlo, g_Qlo);
    cudaGetSymbolAddress((void**)&Khi, g_Khi);
    cudaGetSymbolAddress((void**)&Klo, g_Klo);
    cudaGetSymbolAddress((void**)&Vthi, g_Vthi);
    cudaGetSymbolAddress((void**)&Phi, g_Phi);

    const int SMEM_NT3 = 2 * 4 * TILE_T;   // 81920
    const int SMEM_NT1 = 2 * 2 * TILE_T;   // 40960
    cudaFuncSetAttribute(gemm_mma<3,false>, cudaFuncAttributeMaxDynamicSharedMemorySize, SMEM_NT3);
    cudaFuncSetAttribute(gemm_mma<3,true>,  cudaFuncAttributeMaxDynamicSharedMemorySize, SMEM_NT3);
    cudaFuncSetAttribute(gemm_mma<1,false>, cudaFuncAttributeMaxDynamicSharedMemorySize, SMEM_NT1);

    const size_t WSZ = (size_t)AA * DD;
    const float WS = 16.0f, INV_WS = 1.0f / 16.0f;

    // 1) split X; transpose+split the three weight matrices (scaled by 16)
    split_plain<<<(MTOT * (size_t)DD) / 1024, 256>>>(X, Xhi, Xlo, (size_t)MTOT * DD);
    {
        dim3 g(AA / 32, DD / 32, 1);
        transpose_split<<<g, 256>>>(Wq, Wh + 0 * WSZ, Wl + 0 * WSZ, DD, AA, WS);
        transpose_split<<<g, 256>>>(Wk, Wh + 1 * WSZ, Wl + 1 * WSZ, DD, AA, WS);
        transpose_split<<<g, 256>>>(Wv, Wh + 2 * WSZ, Wl + 2 * WSZ, DD, AA, WS);
    }

    // 2) projections: Q,K 3-term -> fp16 hi/lo; V 1-term -> fp32
    {
        dim3 g(AA / 128, MTOT / 128, 1);
        gemm_mma<3,true><<<g, 256, SMEM_NT3>>>(Xhi, Xlo, Wh + 0*WSZ, Wl + 0*WSZ,
                                               nullptr, Qhi, Qlo, DD, AA, 0, 0, 0, INV_WS);
        gemm_mma<3,true><<<g, 256, SMEM_NT3>>>(Xhi, Xlo, Wh + 1*WSZ, Wl + 1*WSZ,
                                               nullptr, Khi, Klo, DD, AA, 0, 0, 0, INV_WS);
        gemm_mma<1,false><<<g, 256, SMEM_NT1>>>(Xhi, nullptr, Wh + 2*WSZ, nullptr,
                                                Vf, nullptr, nullptr, DD, AA, 0, 0, 0, INV_WS);
    }

    // 3) transpose V per batch to fp16 [A,S], hi only
    {
        dim3 g(AA / 32, SS / 32, BB);
        transpose_hi<<<g, 256>>>(Vf, Vthi, SS, AA,
                                 (long long)SS * AA, (long long)SS * AA);
    }

    // 4) scores (3-term, f16-acc corrections): S = Q @ K^T per batch
    {
        dim3 g(SS / 128, SS / 128, BB);
        gemm_mma<3,false><<<g, 256, SMEM_NT3>>>(Qhi, Qlo, Khi, Klo, Sc, nullptr, nullptr,
                                                AA, SS,
                                                (long long)SS * AA, (long long)SS * AA,
                                                (long long)SS * SS, 1.0f);
    }

    // 5) softmax -> fp16 P (hi only)
    softmax_f16<<<BB * SS, 256>>>(Sc, Phi);

    // 6) output (1-term): O = P @ V per batch
    {
        dim3 g(AA / 128, SS / 128, BB);
        gemm_mma<1,false><<<g, 256, SMEM_NT1>>>(Phi, nullptr, Vthi, nullptr, out, nullptr, nullptr,
                                                SS, AA,
                                                (long long)SS * SS, (long long)AA * SS,
                                                (long long)SS * AA, 1.0f);
    }
}

// round 9
// speedup vs baseline: 1.1510x; 1.1510x over previous
#include <cuda_runtime.h>
#include <cuda_fp16.h>
#include <cstdint>
#include <math.h>

// Problem dims (fixed)
#define BB 4
#define SS 4096
#define DD 1024
#define AA 1024
#define MTOT (BB*SS)   // 16384

// ---------------------------------------------------------------------------
// Device scratch
// ---------------------------------------------------------------------------
__device__ float g_Vf[(size_t)MTOT * AA];                 // 64 MB
__device__ float g_S [(size_t)BB * SS * SS];              // 256 MB scores
__device__ __half g_Xhi[(size_t)MTOT * DD];
__device__ __half g_Xlo[(size_t)MTOT * DD];
__device__ __half g_Wh[3][(size_t)AA * DD];               // (16*W)^T splits [A,D]
__device__ __half g_Wl[3][(size_t)AA * DD];
__device__ __half g_Qhi[(size_t)MTOT * AA];
__device__ __half g_Qlo[(size_t)MTOT * AA];
__device__ __half g_Khi[(size_t)MTOT * AA];
__device__ __half g_Klo[(size_t)MTOT * AA];
__device__ __half g_Vthi[(size_t)BB * AA * SS];           // V^T per batch [A,S]
__device__ __half g_Phi[(size_t)BB * SS * SS];            // 128 MB

// ---------------------------------------------------------------------------
// Helpers
// ---------------------------------------------------------------------------
__device__ __forceinline__ uint32_t smem_u32(const void* p) {
    uint32_t a;
    asm("{ .reg .u64 t; cvta.to.shared.u64 t, %1; cvt.u32.u64 %0, t; }" : "=r"(a) : "l"(p));
    return a;
}

#define CP_ASYNC16(saddr, gaddr) \
    asm volatile("cp.async.cg.shared.global [%0], [%1], 16;" :: "r"(saddr), "l"(gaddr))
#define CP_COMMIT()  asm volatile("cp.async.commit_group;" ::: "memory")
#define CP_WAIT1()   asm volatile("cp.async.wait_group 1;" ::: "memory")
#define CP_WAIT0()   asm volatile("cp.async.wait_group 0;" ::: "memory")

#define MMA_F16(c, a, b) \
    asm volatile("mma.sync.aligned.m16n8k16.row.col.f32.f16.f16.f32 " \
        "{%0,%1,%2,%3}, {%4,%5,%6,%7}, {%8,%9}, {%0,%1,%2,%3};" \
        : "+f"((c)[0]), "+f"((c)[1]), "+f"((c)[2]), "+f"((c)[3]) \
        : "r"((a)[0]), "r"((a)[1]), "r"((a)[2]), "r"((a)[3]), \
          "r"((b)[0]), "r"((b)[1]))

// ---------------------------------------------------------------------------
// HMMA GEMM, fp16 hi/lo split, term count NT (all f32-accumulate):
//   NT=3: AhBh + AlBh + AhBl   (A split, B split)
//   NT=2: AhBh + AlBh          (A split, B hi only)
//   NT=1: AhBh                 (A hi, B hi)
// C[M,N] = A[M,K] * B[N,K]^T, K-major. CTA tile 128x128, KC=32,
// 2-stage cp.async double buffer, 2 CTAs/SM.
// 8 warps as 4(m) x 2(n); warp tile 32x64 = 2 m16 x 8 n8 mma tiles.
// ---------------------------------------------------------------------------
#define KC    32
#define ROWB  80                              // 32 fp16 (64B) + 16B pad
#define TILE_T (128 * ROWB)                   // 10240 B

__device__ __forceinline__ void load_tile32(const __half* __restrict__ g,
                                            int ldK, char* sb, int tid)
{
#pragma unroll
    for (int i = 0; i < 2; i++) {
        int ch = tid + i * 256;               // 0..511
        int row = ch >> 2, c = ch & 3;
        CP_ASYNC16(smem_u32(sb + row * ROWB + c * 16),
                   g + (size_t)row * ldK + c * 8);
    }
}

template <int NT>
__device__ __forceinline__ void load_stage(const __half* pAh, const __half* pAl,
                                           const __half* pBh, const __half* pBl,
                                           int k0, int K, char* sp, int tid)
{
    load_tile32(pAh + k0, K, sp, tid);
    if (NT >= 2) {
        load_tile32(pAl + k0, K, sp + TILE_T,     tid);
        load_tile32(pBh + k0, K, sp + 2 * TILE_T, tid);
        if (NT == 3)
            load_tile32(pBl + k0, K, sp + 3 * TILE_T, tid);
    } else {
        load_tile32(pBh + k0, K, sp + TILE_T, tid);
    }
    CP_COMMIT();
}

template <int NT, bool SPLIT_OUT>
__global__ __launch_bounds__(256, 2)
void gemm_mma(const __half* __restrict__ Ahi, const __half* __restrict__ Alo,
              const __half* __restrict__ Bhi, const __half* __restrict__ Blo,
              float* __restrict__ C,
              __half* __restrict__ Chi, __half* __restrict__ Clo,
              int K, int ldC,
              long long sA, long long sB, long long sC, float oscale)
{
    constexpr int STG = (NT + 1) * TILE_T;
    extern __shared__ __align__(128) char smem[];
    const int tid = threadIdx.x;
    const int wid = tid >> 5, lane = tid & 31;
    const int wm = wid & 3, wn = wid >> 2;    // 4(m) x 2(n)
    const int m0 = blockIdx.y * 128;
    const int n0 = blockIdx.x * 128;

    const __half* pAh = Ahi + (size_t)blockIdx.z * sA + (size_t)m0 * K;
    const __half* pAl = (NT >= 2) ? Alo + (size_t)blockIdx.z * sA + (size_t)m0 * K : nullptr;
    const __half* pBh = Bhi + (size_t)blockIdx.z * sB + (size_t)n0 * K;
    const __half* pBl = (NT == 3) ? Blo + (size_t)blockIdx.z * sB + (size_t)n0 * K : nullptr;

    float acc[2][8][4];
#pragma unroll
    for (int mt = 0; mt < 2; mt++)
#pragma unroll
        for (int nt = 0; nt < 8; nt++)
#pragma unroll
            for (int j = 0; j < 4; j++) acc[mt][nt][j] = 0.0f;

    const int nch = K >> 5;

    load_stage<NT>(pAh, pAl, pBh, pBl, 0,  K, smem,       tid);
    load_stage<NT>(pAh, pAl, pBh, pBl, KC, K, smem + STG, tid);

    const int r  = lane >> 2;        // 0..7
    const int kq = lane & 3;         // 0..3

    for (int c = 0; c < nch; ++c) {
        if (c + 1 < nch) CP_WAIT1(); else CP_WAIT0();
        __syncthreads();

        const char* sp  = smem + (c & 1) * STG;
        const char* sAh = sp;
        const char* sAl = sp + TILE_T;                       // NT>=2
        const char* sBh = sp + (NT >= 2 ? 2 : 1) * TILE_T;
        const char* sBl = sp + 3 * TILE_T;                   // NT==3

#pragma unroll
        for (int ks = 0; ks < 2; ++ks) {
            const int kb = ks * 32 + kq * 4;

            uint32_t ah[2][4], al[2][4];
#pragma unroll
            for (int mt = 0; mt < 2; mt++) {
                const int row = wm * 32 + mt * 16 + r;
                const char* a0 = sAh + row * ROWB + kb;
                const char* a1 = sAh + (row + 8) * ROWB + kb;
                ah[mt][0] = *(const uint32_t*)(a0);
                ah[mt][1] = *(const uint32_t*)(a1);
                ah[mt][2] = *(const uint32_t*)(a0 + 16);
                ah[mt][3] = *(const uint32_t*)(a1 + 16);
                if (NT >= 2) {
                    const char* b0 = sAl + row * ROWB + kb;
                    const char* b1 = sAl + (row + 8) * ROWB + kb;
                    al[mt][0] = *(const uint32_t*)(b0);
                    al[mt][1] = *(const uint32_t*)(b1);
                    al[mt][2] = *(const uint32_t*)(b0 + 16);
                    al[mt][3] = *(const uint32_t*)(b1 + 16);
                }
            }
#pragma unroll
            for (int nt = 0; nt < 8; nt++) {
                const int n = wn * 64 + nt * 8 + r;
                uint32_t bh[2];
                const char* p = sBh + n * ROWB + kb;
                bh[0] = *(const uint32_t*)(p);
                bh[1] = *(const uint32_t*)(p + 16);
#pragma unroll
                for (int mt = 0; mt < 2; mt++) {
                    MMA_F16(acc[mt][nt], ah[mt], bh);
                    if (NT >= 2) MMA_F16(acc[mt][nt], al[mt], bh);
                }
                if (NT == 3) {
                    uint32_t bl[2];
                    const char* q = sBl + n * ROWB + kb;
                    bl[0] = *(const uint32_t*)(q);
                    bl[1] = *(const uint32_t*)(q + 16);
#pragma unroll
                    for (int mt = 0; mt < 2; mt++)
                        MMA_F16(acc[mt][nt], ah[mt], bl);
                }
            }
        }

        if (c + 2 < nch) {
            __syncthreads();
            load_stage<NT>(pAh, pAl, pBh, pBl, (c + 2) * KC, K,
                           smem + (c & 1) * STG, tid);
        }
    }

    // epilogue
    const int cq = (lane & 3) * 2;
    if (!SPLIT_OUT) {
        float* Cw = C + (size_t)blockIdx.z * sC
                      + (size_t)(m0 + wm * 32) * ldC + n0 + wn * 64;
#pragma unroll
        for (int mt = 0; mt < 2; mt++)
#pragma unroll
            for (int nt = 0; nt < 8; nt++) {
                float* p0 = Cw + (size_t)(mt * 16 + r) * ldC + nt * 8 + cq;
                float* p1 = p0 + 8 * (size_t)ldC;
                *(float2*)p0 = make_float2(acc[mt][nt][0] * oscale, acc[mt][nt][1] * oscale);
                *(float2*)p1 = make_float2(acc[mt][nt][2] * oscale, acc[mt][nt][3] * oscale);
            }
    } else {
        const size_t off = (size_t)blockIdx.z * sC
                         + (size_t)(m0 + wm * 32) * ldC + n0 + wn * 64;
        __half* Hw = Chi + off;
        __half* Lw = Clo + off;
#pragma unroll
        for (int mt = 0; mt < 2; mt++)
#pragma unroll
            for (int nt = 0; nt < 8; nt++) {
                const size_t o0 = (size_t)(mt * 16 + r) * ldC + nt * 8 + cq;
                const size_t o1 = o0 + 8 * (size_t)ldC;
                float x0 = acc[mt][nt][0] * oscale, x1 = acc[mt][nt][1] * oscale;
                float x2 = acc[mt][nt][2] * oscale, x3 = acc[mt][nt][3] * oscale;
                __half h0 = __float2half_rn(x0), h1 = __float2half_rn(x1);
                __half h2 = __float2half_rn(x2), h3 = __float2half_rn(x3);
                *(__half2*)(Hw + o0) = __halves2half2(h0, h1);
                *(__half2*)(Hw + o1) = __halves2half2(h2, h3);
                __half l0 = __float2half_rn(x0 - __half2float(h0));
                __half l1 = __float2half_rn(x1 - __half2float(h1));
                __half l2 = __float2half_rn(x2 - __half2float(h2));
                __half l3 = __float2half_rn(x3 - __half2float(h3));
                *(__half2*)(Lw + o0) = __halves2half2(l0, l1);
                *(__half2*)(Lw + o1) = __halves2half2(l2, l3);
            }
    }
}

// ---------------------------------------------------------------------------
// fp32 -> fp16 hi/lo split (elementwise)
// ---------------------------------------------------------------------------
__global__ __launch_bounds__(256)
void split_plain(const float* __restrict__ in, __half* __restrict__ hi,
                 __half* __restrict__ lo, size_t n)
{
    size_t i = ((size_t)blockIdx.x * 256 + threadIdx.x) * 4;
    if (i >= n) return;
    float4 x = *(const float4*)(in + i);
    __half h0 = __float2half_rn(x.x), h1 = __float2half_rn(x.y);
    __half h2 = __float2half_rn(x.z), h3 = __float2half_rn(x.w);
    __half l0 = __float2half_rn(x.x - __half2float(h0));
    __half l1 = __float2half_rn(x.y - __half2float(h1));
    __half l2 = __float2half_rn(x.z - __half2float(h2));
    __half l3 = __float2half_rn(x.w - __half2float(h3));
    *(__half2*)(hi + i)     = __halves2half2(h0, h1);
    *(__half2*)(hi + i + 2) = __halves2half2(h2, h3);
    *(__half2*)(lo + i)     = __halves2half2(l0, l1);
    *(__half2*)(lo + i + 2) = __halves2half2(l2, l3);
}

// ---------------------------------------------------------------------------
// fp32 [R,C] -> transposed, scaled fp16 hi/lo [C,R]
// ---------------------------------------------------------------------------
__global__ __launch_bounds__(256)
void transpose_split(const float* __restrict__ in, __half* __restrict__ hiT,
                     __half* __restrict__ loT, int R, int C, float scale)
{
    __shared__ float t[32][33];
    const int r0 = blockIdx.y * 32, c0 = blockIdx.x * 32;
    const int tx = threadIdx.x & 31, ty = threadIdx.x >> 5;
#pragma unroll
    for (int i = ty; i < 32; i += 8)
        t[i][tx] = in[(size_t)(r0 + i) * C + c0 + tx];
    __syncthreads();
#pragma unroll
    for (int i = ty; i < 32; i += 8) {
        float x = t[tx][i] * scale;
        __half h = __float2half_rn(x);
        __half l = __float2half_rn(x - __half2float(h));
        size_t o = (size_t)(c0 + i) * R + r0 + tx;
        hiT[o] = h; loT[o] = l;
    }
}

// fp32 [R,C] -> transposed fp16 hi only [C,R] (batched via z)
__global__ __launch_bounds__(256)
void transpose_hi(const float* __restrict__ in, __half* __restrict__ hiT,
                  int R, int C, long long sIn, long long sOut)
{
    __shared__ float t[32][33];
    in  += (size_t)blockIdx.z * sIn;
    hiT += (size_t)blockIdx.z * sOut;
    const int r0 = blockIdx.y * 32, c0 = blockIdx.x * 32;
    const int tx = threadIdx.x & 31, ty = threadIdx.x >> 5;
#pragma unroll
    for (int i = ty; i < 32; i += 8)
        t[i][tx] = in[(size_t)(r0 + i) * C + c0 + tx];
    __syncthreads();
#pragma unroll
    for (int i = ty; i < 32; i += 8)
        hiT[(size_t)(c0 + i) * R + r0 + tx] = __float2half_rn(t[tx][i]);
}

// ---------------------------------------------------------------------------
// Row softmax (4096 cols), write fp16 (hi only)
// ---------------------------------------------------------------------------
__global__ __launch_bounds__(256)
void softmax_f16(const float* __restrict__ S, __half* __restrict__ Ph)
{
    const size_t row = blockIdx.x;
    const float* p = S + row * (size_t)SS;
    const int tid = threadIdx.x;

    float4 v[4];
    float m = -INFINITY;
#pragma unroll
    for (int i = 0; i < 4; i++) {
        v[i] = ((const float4*)p)[tid + i * 256];
        m = fmaxf(m, fmaxf(fmaxf(v[i].x, v[i].y), fmaxf(v[i].z, v[i].w)));
    }
    __shared__ float red[256];
    red[tid] = m; __syncthreads();
#pragma unroll
    for (int s = 128; s > 0; s >>= 1) {
        if (tid < s) red[tid] = fmaxf(red[tid], red[tid + s]);
        __syncthreads();
    }
    const float rowmax = red[0];
    __syncthreads();

    float sum = 0.0f;
#pragma unroll
    for (int i = 0; i < 4; i++) {
        v[i].x = __expf(v[i].x - rowmax);
        v[i].y = __expf(v[i].y - rowmax);
        v[i].z = __expf(v[i].z - rowmax);
        v[i].w = __expf(v[i].w - rowmax);
        sum += v[i].x + v[i].y + v[i].z + v[i].w;
    }
    red[tid] = sum; __syncthreads();
#pragma unroll
    for (int s = 128; s > 0; s >>= 1) {
        if (tid < s) red[tid] += red[tid + s];
        __syncthreads();
    }
    const float inv = 1.0f / red[0];
    __syncthreads();

#pragma unroll
    for (int i = 0; i < 4; i++) {
        size_t o = row * (size_t)SS + (size_t)(tid + i * 256) * 4;
        *(__half2*)(Ph + o)     = __halves2half2(__float2half_rn(v[i].x * inv),
                                                 __float2half_rn(v[i].y * inv));
        *(__half2*)(Ph + o + 2) = __halves2half2(__float2half_rn(v[i].z * inv),
                                                 __float2half_rn(v[i].w * inv));
    }
}

// ---------------------------------------------------------------------------
// kernel_launch — graph-capturable pipeline
// ---------------------------------------------------------------------------
extern "C" void kernel_launch(void* const* d_in, const int* in_sizes, int n_in,
                              void* d_out, int out_size)
{
    const float* X  = (const float*)d_in[0];
    const float* Wq = (const float*)d_in[1];
    const float* Wk = (const float*)d_in[2];
    const float* Wv = (const float*)d_in[3];
    float* out = (float*)d_out;

    float *Vf, *Sc;
    __half *Xhi, *Xlo, *Wh, *Wl, *Qhi, *Qlo, *Khi, *Klo, *Vthi, *Phi;
    cudaGetSymbolAddress((void**)&Vf, g_Vf);
    cudaGetSymbolAddress((void**)&Sc, g_S);
    cudaGetSymbolAddress((void**)&Xhi, g_Xhi);
    cudaGetSymbolAddress((void**)&Xlo, g_Xlo);
    cudaGetSymbolAddress((void**)&Wh, g_Wh);
    cudaGetSymbolAddress((void**)&Wl, g_Wl);
    cudaGetSymbolAddress((void**)&Qhi, g_Qhi);
    cudaGetSymbolAddress((void**)&Qlo, g_Qlo);
    cudaGetSymbolAddress((void**)&Khi, g_Khi);
    cudaGetSymbolAddress((void**)&Klo, g_Klo);
    cudaGetSymbolAddress((void**)&Vthi, g_Vthi);
    cudaGetSymbolAddress((void**)&Phi, g_Phi);

    const int SMEM_NT3 = 2 * 4 * TILE_T;   // 81920
    const int SMEM_NT1 = 2 * 2 * TILE_T;   // 40960
    cudaFuncSetAttribute(gemm_mma<3,false>, cudaFuncAttributeMaxDynamicSharedMemorySize, SMEM_NT3);
    cudaFuncSetAttribute(gemm_mma<3,true>,  cudaFuncAttributeMaxDynamicSharedMemorySize, SMEM_NT3);
    cudaFuncSetAttribute(gemm_mma<1,false>, cudaFuncAttributeMaxDynamicSharedMemorySize, SMEM_NT1);

    const size_t WSZ = (size_t)AA * DD;
    const float WS = 16.0f, INV_WS = 1.0f / 16.0f;

    // 1) split X; transpose+split the three weight matrices (scaled by 16)
    split_plain<<<(MTOT * (size_t)DD) / 1024, 256>>>(X, Xhi, Xlo, (size_t)MTOT * DD);
    {
        dim3 g(AA / 32, DD / 32, 1);
        transpose_split<<<g, 256>>>(Wq, Wh + 0 * WSZ, Wl + 0 * WSZ, DD, AA, WS);
        transpose_split<<<g, 256>>>(Wk, Wh + 1 * WSZ, Wl + 1 * WSZ, DD, AA, WS);
        transpose_split<<<g, 256>>>(Wv, Wh + 2 * WSZ, Wl + 2 * WSZ, DD, AA, WS);
    }

    // 2) projections: Q,K 3-term -> fp16 hi/lo; V 1-term -> fp32
    {
        dim3 g(AA / 128, MTOT / 128, 1);
        gemm_mma<3,true><<<g, 256, SMEM_NT3>>>(Xhi, Xlo, Wh + 0*WSZ, Wl + 0*WSZ,
                                               nullptr, Qhi, Qlo, DD, AA, 0, 0, 0, INV_WS);
        gemm_mma<3,true><<<g, 256, SMEM_NT3>>>(Xhi, Xlo, Wh + 1*WSZ, Wl + 1*WSZ,
                                               nullptr, Khi, Klo, DD, AA, 0, 0, 0, INV_WS);
        gemm_mma<1,false><<<g, 256, SMEM_NT1>>>(Xhi, nullptr, Wh + 2*WSZ, nullptr,
                                                Vf, nullptr, nullptr, DD, AA, 0, 0, 0, INV_WS);
    }

    // 3) transpose V per batch to fp16 [A,S], hi only
    {
        dim3 g(AA / 32, SS / 32, BB);
        transpose_hi<<<g, 256>>>(Vf, Vthi, SS, AA,
                                 (long long)SS * AA, (long long)SS * AA);
    }

    // 4) scores (3-term): S = Q @ K^T per batch
    {
        dim3 g(SS / 128, SS / 128, BB);
        gemm_mma<3,false><<<g, 256, SMEM_NT3>>>(Qhi, Qlo, Khi, Klo, Sc, nullptr, nullptr,
                                                AA, SS,
                                                (long long)SS * AA, (long long)SS * AA,
                                                (long long)SS * SS, 1.0f);
    }

    // 5) softmax -> fp16 P (hi only)
    softmax_f16<<<BB * SS, 256>>>(Sc, Phi);

    // 6) output (1-term): O = P @ V per batch
    {
        dim3 g(AA / 128, SS / 128, BB);
        gemm_mma<1,false><<<g, 256, SMEM_NT1>>>(Phi, nullptr, Vthi, nullptr, out, nullptr, nullptr,
                                                SS, AA,
                                                (long long)SS * SS, (long long)AA * SS,
                                                (long long)SS * AA, 1.0f);
    }
}